// round 1
// baseline (speedup 1.0000x reference)
#include <cuda_runtime.h>
#include <math.h>

#define BB   1024
#define TT   64
#define TPB  16          // tokens per block
#define NTH  256
#define NBLK ((BB*TT)/TPB)

__global__ __launch_bounds__(256) void actor_kernel(
    const float* __restrict__ state, const float* __restrict__ noise,
    const float* __restrict__ Wq, const float* __restrict__ Wk, const float* __restrict__ Wv,
    const float* __restrict__ W1, const float* __restrict__ b1,
    const float* __restrict__ W2, const float* __restrict__ b2,
    const float* __restrict__ Wmu, const float* __restrict__ bmu,
    const float* __restrict__ Wls, const float* __restrict__ bls,
    float* __restrict__ out)
{
    __shared__ float s_state[TT][8];
    __shared__ float s_wq[120], s_wk[75], s_wv[75];
    __shared__ float s_x[TPB][24];      // att(15) + state(8), padded
    __shared__ float s_h1[TPB][256];
    __shared__ float s_red[8][TPB][4];  // per-warp head partials
    __shared__ float s_fin[TPB][4];

    const int tid  = threadIdx.x;
    const int blk  = blockIdx.x;
    const int b    = blk / (TT / TPB);
    const int t0   = (blk % (TT / TPB)) * TPB;
    const int warp = tid >> 5;
    const int lane = tid & 31;

    // ---- load state row (64x8) + tiny weights into shared ----
    const float* srow = state + (size_t)b * TT * 8;
    for (int i = tid; i < TT * 8; i += NTH) ((float*)s_state)[i] = srow[i];
    for (int i = tid; i < 120; i += NTH) s_wq[i] = Wq[i];
    if (tid < 75) { s_wk[tid] = Wk[tid]; s_wv[tid] = Wv[tid]; }
    __syncthreads();

    const float INV_SQRT5 = 0.44721359549995793f;

    // ---- attention: warp w handles tokens t0+w and t0+w+8 ----
    #pragma unroll
    for (int pass = 0; pass < TPB / 8; ++pass) {
        const int tok = pass * 8 + warp;   // local token 0..15
        const int t   = t0 + tok;          // global token within row (0..63)

        // q[15] (redundant per lane; shared broadcast reads)
        float q[15];
        #pragma unroll
        for (int m = 0; m < 15; ++m) {
            float a = 0.f;
            #pragma unroll
            for (int i = 0; i < 8; ++i) a = fmaf(s_state[t][i], s_wq[i * 15 + m], a);
            q[m] = a;
        }

        float vl[2][15];
        float sc[2][3];
        #pragma unroll
        for (int p = 0; p < 2; ++p) {
            const int n = lane + 32 * p;        // neighbor slot 0..62
            const bool valid = (n < 63);
            const int nn = valid ? n : 0;
            const int j  = (nn < t) ? nn : nn + 1;

            float ang = -s_state[j][7] + 1.5707963267948966f;
            float s_, c_;
            __sincosf(ang, &s_, &c_);
            const float dx0 = s_state[j][0] - s_state[t][0];
            const float dy0 = s_state[j][1] - s_state[t][1];
            const float dx1 = s_state[j][2] - s_state[t][2];
            const float dy1 = s_state[j][3] - s_state[t][3];
            const float xn0 = dx0 * c_ - dy0 * s_;
            const float yn0 = dx0 * s_ + dy0 * c_;
            const float xn1 = dx1 * c_ - dy1 * s_;
            const float yn1 = dx1 * s_ + dy1 * c_;
            const float r    = sqrtf(xn0 * xn0 + yn0 * yn0);
            const float rinv = 1.f / r;
            const float rt   = 1.f / (1.f + __expf(-(1.f - 5.f * (r - 0.2f))));
            float f[5];
            f[0] = xn0 * rinv; f[1] = yn0 * rinv; f[2] = xn1; f[3] = yn1; f[4] = rt;

            float kk[15];
            #pragma unroll
            for (int hk = 0; hk < 15; ++hk) {
                float k_ = 0.f, v_ = 0.f;
                #pragma unroll
                for (int ff = 0; ff < 5; ++ff) {
                    k_ = fmaf(f[ff], s_wk[ff * 15 + hk], k_);
                    v_ = fmaf(f[ff], s_wv[ff * 15 + hk], v_);
                }
                kk[hk] = k_;
                vl[p][hk] = valid ? v_ : 0.f;
            }
            #pragma unroll
            for (int h = 0; h < 3; ++h) {
                float d = 0.f;
                #pragma unroll
                for (int k = 0; k < 5; ++k) d = fmaf(kk[h * 5 + k], q[h * 5 + k], d);
                sc[p][h] = valid ? d * INV_SQRT5 : -1e30f;
            }
        }

        // softmax over 63 neighbors per head
        float w01[2][3];
        #pragma unroll
        for (int h = 0; h < 3; ++h) {
            float m = fmaxf(sc[0][h], sc[1][h]);
            #pragma unroll
            for (int off = 16; off > 0; off >>= 1)
                m = fmaxf(m, __shfl_xor_sync(0xffffffffu, m, off));
            float e0 = __expf(sc[0][h] - m);
            float e1 = __expf(sc[1][h] - m);
            float s  = e0 + e1;
            #pragma unroll
            for (int off = 16; off > 0; off >>= 1)
                s += __shfl_xor_sync(0xffffffffu, s, off);
            const float si = 1.f / s;
            w01[0][h] = e0 * si;
            w01[1][h] = e1 * si;
        }

        // att[15] = sum_n w * vals
        float att[15];
        #pragma unroll
        for (int h = 0; h < 3; ++h)
            #pragma unroll
            for (int k = 0; k < 5; ++k) {
                int hk = h * 5 + k;
                att[hk] = fmaf(w01[0][h], vl[0][hk], w01[1][h] * vl[1][hk]);
            }
        #pragma unroll
        for (int i = 0; i < 15; ++i)
            #pragma unroll
            for (int off = 16; off > 0; off >>= 1)
                att[i] += __shfl_xor_sync(0xffffffffu, att[i], off);

        if (lane < 15) s_x[tok][lane] = att[lane];
        else if (lane < 23) s_x[tok][lane] = s_state[t][lane - 15];
    }
    __syncthreads();

    // ---- layer 1: x(23) @ W1(23,256) + b1, relu ----
    {
        const int j = tid;
        float acc[TPB];
        const float bb = b1[j];
        #pragma unroll
        for (int k = 0; k < TPB; ++k) acc[k] = bb;
        #pragma unroll
        for (int i = 0; i < 23; ++i) {
            const float wv = W1[i * 256 + j];
            #pragma unroll
            for (int k = 0; k < TPB; ++k) acc[k] = fmaf(s_x[k][i], wv, acc[k]);
        }
        #pragma unroll
        for (int k = 0; k < TPB; ++k) s_h1[k][j] = fmaxf(acc[k], 0.f);
    }
    __syncthreads();

    // ---- layer 2: h1(256) @ W2(256,256) + b2, relu ----
    float h2[TPB];
    {
        const int j = tid;
        const float bb = b2[j];
        #pragma unroll
        for (int k = 0; k < TPB; ++k) h2[k] = bb;
        #pragma unroll 4
        for (int i = 0; i < 256; ++i) {
            const float wv = W2[i * 256 + j];
            #pragma unroll
            for (int k = 0; k < TPB; ++k) h2[k] = fmaf(s_h1[k][i], wv, h2[k]);
        }
        #pragma unroll
        for (int k = 0; k < TPB; ++k) h2[k] = fmaxf(h2[k], 0.f);
    }

    // ---- head dots: per-token [mu0, mu1, ls0, ls1] ----
    {
        const int j = tid;
        const float wm0 = Wmu[j * 2 + 0], wm1 = Wmu[j * 2 + 1];
        const float wl0 = Wls[j * 2 + 0], wl1 = Wls[j * 2 + 1];
        #pragma unroll
        for (int k = 0; k < TPB; ++k) {
            float a0 = h2[k] * wm0;
            float a1 = h2[k] * wm1;
            float a2 = h2[k] * wl0;
            float a3 = h2[k] * wl1;
            #pragma unroll
            for (int off = 16; off > 0; off >>= 1) {
                a0 += __shfl_xor_sync(0xffffffffu, a0, off);
                a1 += __shfl_xor_sync(0xffffffffu, a1, off);
                a2 += __shfl_xor_sync(0xffffffffu, a2, off);
                a3 += __shfl_xor_sync(0xffffffffu, a3, off);
            }
            if (lane == 0) {
                s_red[warp][k][0] = a0; s_red[warp][k][1] = a1;
                s_red[warp][k][2] = a2; s_red[warp][k][3] = a3;
            }
        }
    }
    __syncthreads();
    if (tid < TPB * 4) {
        const int k = tid >> 2, c = tid & 3;
        float s = 0.f;
        #pragma unroll
        for (int w = 0; w < 8; ++w) s += s_red[w][k][c];
        s_fin[k][c] = s;
    }
    __syncthreads();

    // ---- final tanh-Gaussian math, write outputs ----
    if (tid < TPB) {
        const int k = tid;
        const size_t g = (size_t)b * TT + t0 + k;
        const float mu0 = tanhf(s_fin[k][0] + bmu[0]);
        const float mu1 = tanhf(s_fin[k][1] + bmu[1]);
        const float l0  = tanhf(s_fin[k][2] + bls[0]);
        const float l1  = tanhf(s_fin[k][3] + bls[1]);
        const float ls0 = -20.f + 11.f * (l0 + 1.f);
        const float ls1 = -20.f + 11.f * (l1 + 1.f);
        const float sd0 = expf(ls0), sd1 = expf(ls1);
        const float n0 = noise[g * 2 + 0], n1 = noise[g * 2 + 1];
        const float z0 = mu0 + sd0 * n0, z1 = mu1 + sd1 * n1;
        const float a0 = tanhf(z0), a1 = tanhf(z1);
        const float HL2PI = 0.9189385332046727f;  // 0.5*log(2*pi)
        const float lp0 = -0.5f * n0 * n0 - ls0 - HL2PI - logf(1.f - a0 * a0 + 1e-7f);
        const float lp1 = -0.5f * n1 * n1 - ls1 - HL2PI - logf(1.f - a1 * a1 + 1e-7f);
        out[g * 2 + 0] = a0;
        out[g * 2 + 1] = a1;
        out[(size_t)BB * TT * 2 + g] = lp0 + lp1;
    }
}

extern "C" void kernel_launch(void* const* d_in, const int* in_sizes, int n_in,
                              void* d_out, int out_size) {
    const float* state = (const float*)d_in[0];
    const float* noise = (const float*)d_in[1];
    const float* Wq    = (const float*)d_in[2];
    const float* Wk    = (const float*)d_in[3];
    const float* Wv    = (const float*)d_in[4];
    const float* W1    = (const float*)d_in[5];
    const float* b1    = (const float*)d_in[6];
    const float* W2    = (const float*)d_in[7];
    const float* b2    = (const float*)d_in[8];
    const float* Wmu   = (const float*)d_in[9];
    const float* bmu   = (const float*)d_in[10];
    const float* Wls   = (const float*)d_in[11];
    const float* bls   = (const float*)d_in[12];
    actor_kernel<<<NBLK, NTH>>>(state, noise, Wq, Wk, Wv, W1, b1, W2, b2,
                                Wmu, bmu, Wls, bls, (float*)d_out);
}

// round 2
// speedup vs baseline: 1.8003x; 1.8003x over previous
#include <cuda_runtime.h>
#include <math.h>

#define BB   1024
#define TT   64
#define NTOK (BB*TT)

__device__ float g_xbuf[NTOK * 24];   // per-token features: att(15) + state(8), pad 24

// ---------------- packed f32x2 helpers ----------------
__device__ __forceinline__ unsigned long long pack2(float lo, float hi) {
    unsigned long long d;
    asm("mov.b64 %0, {%1,%2};" : "=l"(d) : "r"(__float_as_uint(lo)), "r"(__float_as_uint(hi)));
    return d;
}
__device__ __forceinline__ unsigned long long dup2(float x) {
    unsigned long long d;
    asm("mov.b64 %0, {%1,%1};" : "=l"(d) : "r"(__float_as_uint(x)));
    return d;
}
__device__ __forceinline__ void fma2(unsigned long long& d, unsigned long long a, unsigned long long b) {
    asm("fma.rn.f32x2 %0, %1, %2, %0;" : "+l"(d) : "l"(a), "l"(b));
}
__device__ __forceinline__ void unpack2(unsigned long long d, float& lo, float& hi) {
    unsigned int l, h;
    asm("mov.b64 {%0,%1}, %2;" : "=r"(l), "=r"(h) : "l"(d));
    lo = __uint_as_float(l); hi = __uint_as_float(h);
}

// =====================================================================
// Kernel A: attention -> writes x[23] per token to g_xbuf
// one block per batch row (64 tokens), 8 warps, 8 passes
// =====================================================================
__global__ __launch_bounds__(256) void attn_kernel(
    const float* __restrict__ state,
    const float* __restrict__ Wq, const float* __restrict__ Wk, const float* __restrict__ Wv)
{
    __shared__ float s_state[TT][9];     // padded: conflict-free neighbor reads
    __shared__ float s_cs[TT][2];        // cos/sin per neighbor
    __shared__ float s_wq[120], s_wk[80], s_wv[80];

    const int tid  = threadIdx.x;
    const int b    = blockIdx.x;
    const int warp = tid >> 5;
    const int lane = tid & 31;

    const float* srow = state + (size_t)b * TT * 8;
    for (int i = tid; i < TT * 8; i += 256) s_state[i >> 3][i & 7] = srow[i];
    for (int i = tid; i < 120; i += 256) s_wq[i] = Wq[i];
    if (tid < 75) { s_wk[tid] = Wk[tid]; s_wv[tid] = Wv[tid]; }
    __syncthreads();
    if (tid < TT) {
        float ang = -s_state[tid][7] + 1.5707963267948966f;
        float s_, c_;
        __sincosf(ang, &s_, &c_);
        s_cs[tid][0] = c_; s_cs[tid][1] = s_;
    }
    __syncthreads();

    const float INV_SQRT5 = 0.44721359549995793f;

    #pragma unroll 1
    for (int pass = 0; pass < 8; ++pass) {
        const int t = pass * 8 + warp;      // token 0..63

        // q[15] (broadcast shared reads, redundant per lane)
        float q[15];
        #pragma unroll
        for (int m = 0; m < 15; ++m) {
            float a = 0.f;
            #pragma unroll
            for (int i = 0; i < 8; ++i) a = fmaf(s_state[t][i], s_wq[i * 15 + m], a);
            q[m] = a;
        }

        float vl[2][15];
        float sc[2][3];
        #pragma unroll
        for (int p = 0; p < 2; ++p) {
            const int n = lane + 32 * p;        // neighbor slot 0..62
            const bool valid = (n < 63);
            const int nn = valid ? n : 0;
            const int j  = (nn < t) ? nn : nn + 1;

            const float c_ = s_cs[j][0];
            const float s_ = s_cs[j][1];
            const float dx0 = s_state[j][0] - s_state[t][0];
            const float dy0 = s_state[j][1] - s_state[t][1];
            const float dx1 = s_state[j][2] - s_state[t][2];
            const float dy1 = s_state[j][3] - s_state[t][3];
            const float xn0 = dx0 * c_ - dy0 * s_;
            const float yn0 = dx0 * s_ + dy0 * c_;
            const float xn1 = dx1 * c_ - dy1 * s_;
            const float yn1 = dx1 * s_ + dy1 * c_;
            const float r    = sqrtf(xn0 * xn0 + yn0 * yn0);
            const float rinv = 1.f / r;
            const float rt   = 1.f / (1.f + __expf(-(1.f - 5.f * (r - 0.2f))));
            float f[5];
            f[0] = xn0 * rinv; f[1] = yn0 * rinv; f[2] = xn1; f[3] = yn1; f[4] = rt;

            float kk[15];
            #pragma unroll
            for (int hk = 0; hk < 15; ++hk) {
                float k_ = 0.f, v_ = 0.f;
                #pragma unroll
                for (int ff = 0; ff < 5; ++ff) {
                    k_ = fmaf(f[ff], s_wk[ff * 15 + hk], k_);
                    v_ = fmaf(f[ff], s_wv[ff * 15 + hk], v_);
                }
                kk[hk] = k_;
                vl[p][hk] = valid ? v_ : 0.f;
            }
            #pragma unroll
            for (int h = 0; h < 3; ++h) {
                float d = 0.f;
                #pragma unroll
                for (int k = 0; k < 5; ++k) d = fmaf(kk[h * 5 + k], q[h * 5 + k], d);
                sc[p][h] = valid ? d * INV_SQRT5 : -1e30f;
            }
        }

        // softmax over 63 neighbors per head
        float w01[2][3];
        #pragma unroll
        for (int h = 0; h < 3; ++h) {
            float m = fmaxf(sc[0][h], sc[1][h]);
            #pragma unroll
            for (int off = 16; off > 0; off >>= 1)
                m = fmaxf(m, __shfl_xor_sync(0xffffffffu, m, off));
            float e0 = __expf(sc[0][h] - m);
            float e1 = __expf(sc[1][h] - m);
            float s  = e0 + e1;
            #pragma unroll
            for (int off = 16; off > 0; off >>= 1)
                s += __shfl_xor_sync(0xffffffffu, s, off);
            const float si = 1.f / s;
            w01[0][h] = e0 * si;
            w01[1][h] = e1 * si;
        }

        float att[15];
        #pragma unroll
        for (int h = 0; h < 3; ++h)
            #pragma unroll
            for (int k = 0; k < 5; ++k) {
                int hk = h * 5 + k;
                att[hk] = fmaf(w01[0][h], vl[0][hk], w01[1][h] * vl[1][hk]);
            }
        #pragma unroll
        for (int i = 0; i < 15; ++i)
            #pragma unroll
            for (int off = 16; off > 0; off >>= 1)
                att[i] += __shfl_xor_sync(0xffffffffu, att[i], off);

        const size_t g = (size_t)b * TT + t;
        if (lane < 15) g_xbuf[g * 24 + lane] = att[lane];
        else if (lane < 23) g_xbuf[g * 24 + lane] = s_state[t][lane - 15];
    }
}

// =====================================================================
// Kernel B: MLP (23->256->256) + heads, packed f32x2 GEMM
// 32 tokens/block, 256 threads; thread = 4 token-pairs x 4 units (stride 64)
// =====================================================================
#define TOKB 32

__global__ __launch_bounds__(256, 2) void mlp_kernel(
    const float* __restrict__ noise,
    const float* __restrict__ W1, const float* __restrict__ b1,
    const float* __restrict__ W2, const float* __restrict__ b2,
    const float* __restrict__ Wmu, const float* __restrict__ bmu,
    const float* __restrict__ Wls, const float* __restrict__ bls,
    float* __restrict__ out)
{
    __shared__ float2 s_xp[16][24];      // token-pair-packed x
    __shared__ float2 s_h1p[16][260];    // token-pair-packed h1 (pad 260)
    __shared__ float  s_red[8][8][4];
    __shared__ float  s_fin[TOKB][4];

    const int tid    = threadIdx.x;
    const int g0     = blockIdx.x * TOKB;
    const int t_unit = tid & 63;         // 0..63
    const int t_tok  = tid >> 6;         // 0..3  (8 tokens each)
    const int warp   = tid >> 5;
    const int lane   = tid & 31;

    // ---- stage x pairs ----
    for (int idx = tid; idx < TOKB * 24; idx += 256) {
        const int tok = idx / 24, f = idx % 24;
        const float v = (f < 23) ? g_xbuf[(size_t)(g0 + tok) * 24 + f] : 0.f;
        ((float*)s_xp)[(tok >> 1) * 48 + f * 2 + (tok & 1)] = v;
    }
    __syncthreads();

    unsigned long long acc[4][4];   // [pair][unit]

    // ---- layer 1: K=23 ----
    #pragma unroll
    for (int uu = 0; uu < 4; ++uu) {
        const float bb = b1[t_unit + 64 * uu];
        #pragma unroll
        for (int p = 0; p < 4; ++p) acc[p][uu] = dup2(bb);
    }
    #pragma unroll 1
    for (int i = 0; i < 23; ++i) {
        unsigned long long a[4];
        #pragma unroll
        for (int p = 0; p < 4; ++p)
            a[p] = *(const unsigned long long*)&s_xp[t_tok * 4 + p][i];
        #pragma unroll
        for (int uu = 0; uu < 4; ++uu) {
            const unsigned long long wd = dup2(W1[i * 256 + t_unit + 64 * uu]);
            #pragma unroll
            for (int p = 0; p < 4; ++p) fma2(acc[p][uu], a[p], wd);
        }
    }
    // relu + store paired h1
    #pragma unroll
    for (int p = 0; p < 4; ++p)
        #pragma unroll
        for (int uu = 0; uu < 4; ++uu) {
            float lo, hi; unpack2(acc[p][uu], lo, hi);
            s_h1p[t_tok * 4 + p][t_unit + 64 * uu] =
                make_float2(fmaxf(lo, 0.f), fmaxf(hi, 0.f));
        }
    __syncthreads();

    // ---- layer 2: K=256 ----
    #pragma unroll
    for (int uu = 0; uu < 4; ++uu) {
        const float bb = b2[t_unit + 64 * uu];
        #pragma unroll
        for (int p = 0; p < 4; ++p) acc[p][uu] = dup2(bb);
    }
    #pragma unroll 4
    for (int i = 0; i < 256; ++i) {
        unsigned long long a[4];
        #pragma unroll
        for (int p = 0; p < 4; ++p)
            a[p] = *(const unsigned long long*)&s_h1p[t_tok * 4 + p][i];
        #pragma unroll
        for (int uu = 0; uu < 4; ++uu) {
            const unsigned long long wd = dup2(W2[i * 256 + t_unit + 64 * uu]);
            #pragma unroll
            for (int p = 0; p < 4; ++p) fma2(acc[p][uu], a[p], wd);
        }
    }

    // ---- heads: partial [tok][mu0,mu1,ls0,ls1] over owned units ----
    float part[8][4];
    #pragma unroll
    for (int k = 0; k < 8; ++k)
        #pragma unroll
        for (int c = 0; c < 4; ++c) part[k][c] = 0.f;

    #pragma unroll
    for (int uu = 0; uu < 4; ++uu) {
        const int u = t_unit + 64 * uu;
        const float wm0 = Wmu[u * 2 + 0], wm1 = Wmu[u * 2 + 1];
        const float wl0 = Wls[u * 2 + 0], wl1 = Wls[u * 2 + 1];
        #pragma unroll
        for (int p = 0; p < 4; ++p) {
            float lo, hi; unpack2(acc[p][uu], lo, hi);
            lo = fmaxf(lo, 0.f); hi = fmaxf(hi, 0.f);
            part[2 * p + 0][0] = fmaf(lo, wm0, part[2 * p + 0][0]);
            part[2 * p + 0][1] = fmaf(lo, wm1, part[2 * p + 0][1]);
            part[2 * p + 0][2] = fmaf(lo, wl0, part[2 * p + 0][2]);
            part[2 * p + 0][3] = fmaf(lo, wl1, part[2 * p + 0][3]);
            part[2 * p + 1][0] = fmaf(hi, wm0, part[2 * p + 1][0]);
            part[2 * p + 1][1] = fmaf(hi, wm1, part[2 * p + 1][1]);
            part[2 * p + 1][2] = fmaf(hi, wl0, part[2 * p + 1][2]);
            part[2 * p + 1][3] = fmaf(hi, wl1, part[2 * p + 1][3]);
        }
    }
    #pragma unroll
    for (int k = 0; k < 8; ++k)
        #pragma unroll
        for (int c = 0; c < 4; ++c)
            #pragma unroll
            for (int off = 16; off > 0; off >>= 1)
                part[k][c] += __shfl_xor_sync(0xffffffffu, part[k][c], off);
    if (lane == 0) {
        #pragma unroll
        for (int k = 0; k < 8; ++k)
            #pragma unroll
            for (int c = 0; c < 4; ++c) s_red[warp][k][c] = part[k][c];
    }
    __syncthreads();
    if (tid < TOKB * 4) {
        const int tok = tid >> 2, c = tid & 3;
        const int w0 = (tok >> 3) * 2, l = tok & 7;
        s_fin[tok][c] = s_red[w0][l][c] + s_red[w0 + 1][l][c];
    }
    __syncthreads();

    // ---- final tanh-Gaussian math ----
    if (tid < TOKB) {
        const int k = tid;
        const size_t g = (size_t)g0 + k;
        const float mu0 = tanhf(s_fin[k][0] + bmu[0]);
        const float mu1 = tanhf(s_fin[k][1] + bmu[1]);
        const float l0  = tanhf(s_fin[k][2] + bls[0]);
        const float l1  = tanhf(s_fin[k][3] + bls[1]);
        const float ls0 = -20.f + 11.f * (l0 + 1.f);
        const float ls1 = -20.f + 11.f * (l1 + 1.f);
        const float sd0 = expf(ls0), sd1 = expf(ls1);
        const float n0 = noise[g * 2 + 0], n1 = noise[g * 2 + 1];
        const float z0 = mu0 + sd0 * n0, z1 = mu1 + sd1 * n1;
        const float a0 = tanhf(z0), a1 = tanhf(z1);
        const float HL2PI = 0.9189385332046727f;
        const float lp0 = -0.5f * n0 * n0 - ls0 - HL2PI - logf(1.f - a0 * a0 + 1e-7f);
        const float lp1 = -0.5f * n1 * n1 - ls1 - HL2PI - logf(1.f - a1 * a1 + 1e-7f);
        out[g * 2 + 0] = a0;
        out[g * 2 + 1] = a1;
        out[(size_t)NTOK * 2 + g] = lp0 + lp1;
    }
}

extern "C" void kernel_launch(void* const* d_in, const int* in_sizes, int n_in,
                              void* d_out, int out_size) {
    const float* state = (const float*)d_in[0];
    const float* noise = (const float*)d_in[1];
    const float* Wq    = (const float*)d_in[2];
    const float* Wk    = (const float*)d_in[3];
    const float* Wv    = (const float*)d_in[4];
    const float* W1    = (const float*)d_in[5];
    const float* b1    = (const float*)d_in[6];
    const float* W2    = (const float*)d_in[7];
    const float* b2    = (const float*)d_in[8];
    const float* Wmu   = (const float*)d_in[9];
    const float* bmu   = (const float*)d_in[10];
    const float* Wls   = (const float*)d_in[11];
    const float* bls   = (const float*)d_in[12];

    attn_kernel<<<BB, 256>>>(state, Wq, Wk, Wv);
    mlp_kernel<<<NTOK / TOKB, 256>>>(noise, W1, b1, W2, b2, Wmu, bmu, Wls, bls,
                                     (float*)d_out);
}

// round 3
// speedup vs baseline: 2.3272x; 1.2927x over previous
#include <cuda_runtime.h>
#include <math.h>

#define BB   1024
#define TT   64
#define NTOK (BB*TT)

__device__ float  g_xbuf[NTOK * 24];        // per-token x: att(15)+state(8)
__device__ float2 g_w2p[128 * 256];         // W2 packed over k-pairs
__device__ float2 g_w1p[12 * 256];          // W1 packed over k-pairs (k=23 -> pad 24)

typedef unsigned long long ull;

__device__ __forceinline__ ull dup2(float x) {
    ull d;
    asm("mov.b64 %0, {%1,%1};" : "=l"(d) : "r"(__float_as_uint(x)));
    return d;
}
__device__ __forceinline__ void fma2(ull& d, ull a, ull b) {
    asm("fma.rn.f32x2 %0, %1, %2, %0;" : "+l"(d) : "l"(a), "l"(b));
}
__device__ __forceinline__ void unpack2(ull d, float& lo, float& hi) {
    unsigned int l, h;
    asm("mov.b64 {%0,%1}, %2;" : "=r"(l), "=r"(h) : "l"(d));
    lo = __uint_as_float(l); hi = __uint_as_float(h);
}

// =====================================================================
// weight pack kernel
// =====================================================================
__global__ void pack_kernel(const float* __restrict__ W1, const float* __restrict__ W2) {
    const int idx = blockIdx.x * 256 + threadIdx.x;
    if (idx < 128 * 256) {
        const int k2 = idx >> 8, u = idx & 255;
        g_w2p[idx] = make_float2(W2[(2 * k2) * 256 + u], W2[(2 * k2 + 1) * 256 + u]);
    }
    if (idx < 12 * 256) {
        const int k2 = idx >> 8, u = idx & 255;
        const float hi = (2 * k2 + 1 < 23) ? W1[(2 * k2 + 1) * 256 + u] : 0.f;
        g_w1p[idx] = make_float2(W1[(2 * k2) * 256 + u], hi);
    }
}

// =====================================================================
// Kernel A: attention (refactored: qk-fold + post-reduce V projection)
// one block per batch row, warp per token, 8 passes
// =====================================================================
__global__ __launch_bounds__(256) void attn_kernel(
    const float* __restrict__ state,
    const float* __restrict__ Wq, const float* __restrict__ Wk, const float* __restrict__ Wv)
{
    __shared__ float s_state[TT][9];
    __shared__ float s_cs[TT][2];
    __shared__ float s_A[8][15];        // A[i][h*5+ff] = sum_k Wq[i][h5+k]*Wk[ff][h5+k]
    __shared__ float s_qk[TT][16];      // qk[t][h*5+ff]
    __shared__ float s_wv[80];
    __shared__ float s_wf[8][16];

    const int tid  = threadIdx.x;
    const int b    = blockIdx.x;
    const int warp = tid >> 5;
    const int lane = tid & 31;

    const float* srow = state + (size_t)b * TT * 8;
    for (int i = tid; i < TT * 8; i += 256) s_state[i >> 3][i & 7] = srow[i];
    if (tid < 75) s_wv[tid] = Wv[tid];
    if (tid < 120) {
        const int i = tid / 15, hf = tid % 15;
        const int h = hf / 5, ff = hf % 5;
        float a = 0.f;
        #pragma unroll
        for (int k = 0; k < 5; ++k)
            a = fmaf(Wq[i * 15 + h * 5 + k], Wk[ff * 15 + h * 5 + k], a);
        s_A[i][hf] = a;
    }
    __syncthreads();
    if (tid < TT) {
        float ang = -s_state[tid][7] + 1.5707963267948966f;
        float s_, c_;
        __sincosf(ang, &s_, &c_);
        s_cs[tid][0] = c_; s_cs[tid][1] = s_;
    }
    for (int item = tid; item < TT * 15; item += 256) {
        const int t = item / 15, hf = item % 15;
        float a = 0.f;
        #pragma unroll
        for (int i = 0; i < 8; ++i) a = fmaf(s_state[t][i], s_A[i][hf], a);
        s_qk[t][hf] = a;
    }
    __syncthreads();

    const float INV_SQRT5 = 0.44721359549995793f;

    #pragma unroll 1
    for (int pass = 0; pass < 8; ++pass) {
        const int t = pass * 8 + warp;

        float f0[5], f1[5];
        float sc[2][3];
        #pragma unroll
        for (int p = 0; p < 2; ++p) {
            const int n = lane + 32 * p;
            const bool valid = (n < 63);
            const int nn = valid ? n : 0;
            const int j  = (nn < t) ? nn : nn + 1;

            const float c_ = s_cs[j][0];
            const float s_ = s_cs[j][1];
            const float dx0 = s_state[j][0] - s_state[t][0];
            const float dy0 = s_state[j][1] - s_state[t][1];
            const float dx1 = s_state[j][2] - s_state[t][2];
            const float dy1 = s_state[j][3] - s_state[t][3];
            const float xn0 = dx0 * c_ - dy0 * s_;
            const float yn0 = dx0 * s_ + dy0 * c_;
            const float xn1 = dx1 * c_ - dy1 * s_;
            const float yn1 = dx1 * s_ + dy1 * c_;
            const float r    = sqrtf(xn0 * xn0 + yn0 * yn0);
            const float rinv = 1.f / r;
            const float rt   = 1.f / (1.f + __expf(-(1.f - 5.f * (r - 0.2f))));
            float f[5];
            f[0] = valid ? xn0 * rinv : 0.f;
            f[1] = valid ? yn0 * rinv : 0.f;
            f[2] = valid ? xn1 : 0.f;
            f[3] = valid ? yn1 : 0.f;
            f[4] = valid ? rt  : 0.f;
            #pragma unroll
            for (int ff = 0; ff < 5; ++ff) { if (p == 0) f0[ff] = f[ff]; else f1[ff] = f[ff]; }

            #pragma unroll
            for (int h = 0; h < 3; ++h) {
                float d = 0.f;
                #pragma unroll
                for (int ff = 0; ff < 5; ++ff) d = fmaf(f[ff], s_qk[t][h * 5 + ff], d);
                sc[p][h] = valid ? d * INV_SQRT5 : -1e30f;
            }
        }

        // softmax over 63 neighbors per head
        float w01[2][3];
        #pragma unroll
        for (int h = 0; h < 3; ++h) {
            float m = fmaxf(sc[0][h], sc[1][h]);
            #pragma unroll
            for (int off = 16; off > 0; off >>= 1)
                m = fmaxf(m, __shfl_xor_sync(0xffffffffu, m, off));
            float e0 = __expf(sc[0][h] - m);
            float e1 = __expf(sc[1][h] - m);
            float s  = e0 + e1;
            #pragma unroll
            for (int off = 16; off > 0; off >>= 1)
                s += __shfl_xor_sync(0xffffffffu, s, off);
            const float si = 1.f / s;
            w01[0][h] = e0 * si;
            w01[1][h] = e1 * si;
        }

        // weighted feature sums wf[h][ff], reduce over warp
        float wf[15];
        #pragma unroll
        for (int h = 0; h < 3; ++h)
            #pragma unroll
            for (int ff = 0; ff < 5; ++ff)
                wf[h * 5 + ff] = fmaf(w01[0][h], f0[ff], w01[1][h] * f1[ff]);
        #pragma unroll
        for (int i = 0; i < 15; ++i)
            #pragma unroll
            for (int off = 16; off > 0; off >>= 1)
                wf[i] += __shfl_xor_sync(0xffffffffu, wf[i], off);

        if (lane == 0) {
            #pragma unroll
            for (int i = 0; i < 15; ++i) s_wf[warp][i] = wf[i];
        }
        __syncwarp();

        const size_t g = (size_t)b * TT + t;
        if (lane < 15) {
            const int h = lane / 5;
            float a = 0.f;
            #pragma unroll
            for (int ff = 0; ff < 5; ++ff)
                a = fmaf(s_wf[warp][h * 5 + ff], s_wv[ff * 15 + lane], a);
            g_xbuf[g * 24 + lane] = a;
        } else if (lane < 23) {
            g_xbuf[g * 24 + lane] = s_state[t][lane - 15];
        }
    }
}

// =====================================================================
// Kernel B: MLP + heads, k-paired FFMA2 GEMM
// 32 tokens/block, 256 threads; thread = 8 tokens x 4 units
// =====================================================================
#define TOKB 32

__global__ __launch_bounds__(256, 2) void mlp_kernel(
    const float* __restrict__ noise,
    const float* __restrict__ b1, const float* __restrict__ b2,
    const float* __restrict__ Wmu, const float* __restrict__ bmu,
    const float* __restrict__ Wls, const float* __restrict__ bls,
    float* __restrict__ out)
{
    __shared__ float  s_x[TOKB][24];
    __shared__ float2 s_h1p2[128][34];   // [k2][token] pairs (k even, k odd); pad 34
    __shared__ float  s_red[8][8][4];
    __shared__ float  s_fin[TOKB][4];

    const int tid    = threadIdx.x;
    const int g0     = blockIdx.x * TOKB;
    const int t_unit = tid & 63;         // 64 threads x 4 units (stride 64)
    const int t_grp  = tid >> 6;         // 4 groups x 8 tokens
    const int warp   = tid >> 5;
    const int lane   = tid & 31;
    const int tok0   = t_grp * 8;

    for (int idx = tid; idx < TOKB * 24; idx += 256) {
        const int tok = idx / 24, f = idx % 24;
        s_x[tok][f] = (f < 23) ? g_xbuf[(size_t)(g0 + tok) * 24 + f] : 0.f;
    }
    __syncthreads();

    ull acc[8][4];   // [token][unit] : (even-k partial, odd-k partial)

    // ---- layer 1: K=24 (padded), 12 k2 iters ----
    #pragma unroll
    for (int j = 0; j < 8; ++j)
        #pragma unroll
        for (int uu = 0; uu < 4; ++uu) acc[j][uu] = 0ull;
    #pragma unroll
    for (int k2 = 0; k2 < 12; ++k2) {
        ull a[8];
        #pragma unroll
        for (int j = 0; j < 8; ++j)
            a[j] = *(const ull*)&s_x[tok0 + j][2 * k2];
        ull w[4];
        #pragma unroll
        for (int uu = 0; uu < 4; ++uu)
            w[uu] = *(const ull*)&g_w1p[k2 * 256 + t_unit + 64 * uu];
        #pragma unroll
        for (int uu = 0; uu < 4; ++uu)
            #pragma unroll
            for (int j = 0; j < 8; ++j) fma2(acc[j][uu], a[j], w[uu]);
    }
    // relu(lo+hi+b1) -> paired shared layout for layer 2
    {
        float bb[4];
        #pragma unroll
        for (int uu = 0; uu < 4; ++uu) bb[uu] = b1[t_unit + 64 * uu];
        #pragma unroll
        for (int uu = 0; uu < 4; ++uu) {
            const int u = t_unit + 64 * uu;
            #pragma unroll
            for (int j = 0; j < 8; ++j) {
                float lo, hi; unpack2(acc[j][uu], lo, hi);
                const float h = fmaxf(lo + hi + bb[uu], 0.f);
                ((float*)&s_h1p2[u >> 1][tok0 + j])[u & 1] = h;
            }
        }
    }
    __syncthreads();

    // ---- layer 2: K=256, 128 k2 iters ----
    #pragma unroll
    for (int j = 0; j < 8; ++j)
        #pragma unroll
        for (int uu = 0; uu < 4; ++uu) acc[j][uu] = 0ull;
    #pragma unroll 2
    for (int k2 = 0; k2 < 128; ++k2) {
        ull a[8];
        #pragma unroll
        for (int m = 0; m < 4; ++m) {
            ulonglong2 v = *(const ulonglong2*)&s_h1p2[k2][tok0 + 2 * m];
            a[2 * m] = v.x; a[2 * m + 1] = v.y;
        }
        ull w[4];
        #pragma unroll
        for (int uu = 0; uu < 4; ++uu)
            w[uu] = *(const ull*)&g_w2p[k2 * 256 + t_unit + 64 * uu];
        #pragma unroll
        for (int uu = 0; uu < 4; ++uu)
            #pragma unroll
            for (int j = 0; j < 8; ++j) fma2(acc[j][uu], a[j], w[uu]);
    }

    // ---- heads: h2 = relu(lo+hi+b2); partial dots ----
    float part[8][4];
    #pragma unroll
    for (int j = 0; j < 8; ++j)
        #pragma unroll
        for (int c = 0; c < 4; ++c) part[j][c] = 0.f;

    #pragma unroll
    for (int uu = 0; uu < 4; ++uu) {
        const int u = t_unit + 64 * uu;
        const float bb = b2[u];
        const float wm0 = Wmu[u * 2 + 0], wm1 = Wmu[u * 2 + 1];
        const float wl0 = Wls[u * 2 + 0], wl1 = Wls[u * 2 + 1];
        #pragma unroll
        for (int j = 0; j < 8; ++j) {
            float lo, hi; unpack2(acc[j][uu], lo, hi);
            const float h = fmaxf(lo + hi + bb, 0.f);
            part[j][0] = fmaf(h, wm0, part[j][0]);
            part[j][1] = fmaf(h, wm1, part[j][1]);
            part[j][2] = fmaf(h, wl0, part[j][2]);
            part[j][3] = fmaf(h, wl1, part[j][3]);
        }
    }
    #pragma unroll
    for (int j = 0; j < 8; ++j)
        #pragma unroll
        for (int c = 0; c < 4; ++c)
            #pragma unroll
            for (int off = 16; off > 0; off >>= 1)
                part[j][c] += __shfl_xor_sync(0xffffffffu, part[j][c], off);
    if (lane == 0) {
        #pragma unroll
        for (int j = 0; j < 8; ++j)
            #pragma unroll
            for (int c = 0; c < 4; ++c) s_red[warp][j][c] = part[j][c];
    }
    __syncthreads();
    if (tid < TOKB * 4) {
        const int tok = tid >> 2, c = tid & 3;
        const int gw = (tok >> 3) * 2, j = tok & 7;
        s_fin[tok][c] = s_red[gw][j][c] + s_red[gw + 1][j][c];
    }
    __syncthreads();

    if (tid < TOKB) {
        const int k = tid;
        const size_t g = (size_t)g0 + k;
        const float mu0 = tanhf(s_fin[k][0] + bmu[0]);
        const float mu1 = tanhf(s_fin[k][1] + bmu[1]);
        const float l0  = tanhf(s_fin[k][2] + bls[0]);
        const float l1  = tanhf(s_fin[k][3] + bls[1]);
        const float ls0 = -20.f + 11.f * (l0 + 1.f);
        const float ls1 = -20.f + 11.f * (l1 + 1.f);
        const float sd0 = expf(ls0), sd1 = expf(ls1);
        const float n0 = noise[g * 2 + 0], n1 = noise[g * 2 + 1];
        const float z0 = mu0 + sd0 * n0, z1 = mu1 + sd1 * n1;
        const float a0 = tanhf(z0), a1 = tanhf(z1);
        const float HL2PI = 0.9189385332046727f;
        const float lp0 = -0.5f * n0 * n0 - ls0 - HL2PI - logf(1.f - a0 * a0 + 1e-7f);
        const float lp1 = -0.5f * n1 * n1 - ls1 - HL2PI - logf(1.f - a1 * a1 + 1e-7f);
        out[g * 2 + 0] = a0;
        out[g * 2 + 1] = a1;
        out[(size_t)NTOK * 2 + g] = lp0 + lp1;
    }
}

extern "C" void kernel_launch(void* const* d_in, const int* in_sizes, int n_in,
                              void* d_out, int out_size) {
    const float* state = (const float*)d_in[0];
    const float* noise = (const float*)d_in[1];
    const float* Wq    = (const float*)d_in[2];
    const float* Wk    = (const float*)d_in[3];
    const float* Wv    = (const float*)d_in[4];
    const float* W1    = (const float*)d_in[5];
    const float* b1    = (const float*)d_in[6];
    const float* W2    = (const float*)d_in[7];
    const float* b2    = (const float*)d_in[8];
    const float* Wmu   = (const float*)d_in[9];
    const float* bmu   = (const float*)d_in[10];
    const float* Wls   = (const float*)d_in[11];
    const float* bls   = (const float*)d_in[12];

    pack_kernel<<<128, 256>>>(W1, W2);
    attn_kernel<<<BB, 256>>>(state, Wq, Wk, Wv);
    mlp_kernel<<<NTOK / TOKB, 256>>>(noise, b1, b2, Wmu, bmu, Wls, bls,
                                     (float*)d_out);
}

// round 5
// speedup vs baseline: 4.2569x; 1.8292x over previous
#include <cuda_runtime.h>
#include <cuda_bf16.h>
#include <math.h>

#define BB   1024
#define TT   64
#define NTOK (BB*TT)

typedef unsigned int u32;

__device__ float g_xbuf[NTOK * 24];

// padded bf16 weight images (row-major with pad baked in)
// W1^T: [256 n][40 k]  (k>=23 zero)       per precision
// W2^T: [4 chunk][256 n][72 k] (kl>=64 0) per precision
__device__ __align__(16) __nv_bfloat16 g_w1_hi[256 * 40];
__device__ __align__(16) __nv_bfloat16 g_w1_lo[256 * 40];
__device__ __align__(16) __nv_bfloat16 g_w2_hi[4 * 256 * 72];
__device__ __align__(16) __nv_bfloat16 g_w2_lo[4 * 256 * 72];

__device__ __forceinline__ u32 smem_u32(const void* p) {
    u32 a;
    asm("{ .reg .u64 t; cvta.to.shared.u64 t, %1; cvt.u32.u64 %0, t; }" : "=r"(a) : "l"(p));
    return a;
}
__device__ __forceinline__ void ldsm_x4(u32* r, u32 addr) {
    asm volatile("ldmatrix.sync.aligned.m8n8.x4.shared.b16 {%0,%1,%2,%3}, [%4];"
                 : "=r"(r[0]), "=r"(r[1]), "=r"(r[2]), "=r"(r[3]) : "r"(addr));
}
__device__ __forceinline__ void mma16816(float* d, const u32* a, u32 b0, u32 b1) {
    asm volatile(
        "mma.sync.aligned.m16n8k16.row.col.f32.bf16.bf16.f32 "
        "{%0,%1,%2,%3}, {%4,%5,%6,%7}, {%8,%9}, {%0,%1,%2,%3};"
        : "+f"(d[0]), "+f"(d[1]), "+f"(d[2]), "+f"(d[3])
        : "r"(a[0]), "r"(a[1]), "r"(a[2]), "r"(a[3]), "r"(b0), "r"(b1));
}
__device__ __forceinline__ u32 pack_hi(float a, float b, float& ra, float& rb) {
    const __nv_bfloat16 ha = __float2bfloat16(a);
    const __nv_bfloat16 hb = __float2bfloat16(b);
    ra = a - __bfloat162float(ha);
    rb = b - __bfloat162float(hb);
    return (u32)__bfloat16_as_ushort(ha) | ((u32)__bfloat16_as_ushort(hb) << 16);
}
__device__ __forceinline__ u32 pack_bf(float a, float b) {
    return (u32)__bfloat16_as_ushort(__float2bfloat16(a)) |
           ((u32)__bfloat16_as_ushort(__float2bfloat16(b)) << 16);
}

// =====================================================================
// pack kernel
// =====================================================================
__global__ void pack_kernel(const float* __restrict__ W1, const float* __restrict__ W2) {
    const int idx = blockIdx.x * 256 + threadIdx.x;
    if (idx < 4 * 256 * 72) {
        const int c = idx / 18432, r = idx % 18432;
        const int n = r / 72, kl = r % 72;
        const float w = (kl < 64) ? W2[(c * 64 + kl) * 256 + n] : 0.f;
        const __nv_bfloat16 hi = __float2bfloat16(w);
        g_w2_hi[idx] = hi;
        g_w2_lo[idx] = __float2bfloat16(w - __bfloat162float(hi));
    }
    if (idx < 256 * 40) {
        const int n = idx / 40, k = idx % 40;
        const float w = (k < 23) ? W1[k * 256 + n] : 0.f;
        const __nv_bfloat16 hi = __float2bfloat16(w);
        g_w1_hi[idx] = hi;
        g_w1_lo[idx] = __float2bfloat16(w - __bfloat162float(hi));
    }
}

// =====================================================================
// Kernel A: attention (unchanged — proven at ~95us)
// =====================================================================
__global__ __launch_bounds__(256) void attn_kernel(
    const float* __restrict__ state,
    const float* __restrict__ Wq, const float* __restrict__ Wk, const float* __restrict__ Wv)
{
    __shared__ float s_state[TT][9];
    __shared__ float s_cs[TT][2];
    __shared__ float s_A[8][15];
    __shared__ float s_qk[TT][16];
    __shared__ float s_wv[80];
    __shared__ float s_wf[8][16];

    const int tid  = threadIdx.x;
    const int b    = blockIdx.x;
    const int warp = tid >> 5;
    const int lane = tid & 31;

    const float* srow = state + (size_t)b * TT * 8;
    for (int i = tid; i < TT * 8; i += 256) s_state[i >> 3][i & 7] = srow[i];
    if (tid < 75) s_wv[tid] = Wv[tid];
    if (tid < 120) {
        const int i = tid / 15, hf = tid % 15;
        const int h = hf / 5, ff = hf % 5;
        float a = 0.f;
        #pragma unroll
        for (int k = 0; k < 5; ++k)
            a = fmaf(Wq[i * 15 + h * 5 + k], Wk[ff * 15 + h * 5 + k], a);
        s_A[i][hf] = a;
    }
    __syncthreads();
    if (tid < TT) {
        float ang = -s_state[tid][7] + 1.5707963267948966f;
        float s_, c_;
        __sincosf(ang, &s_, &c_);
        s_cs[tid][0] = c_; s_cs[tid][1] = s_;
    }
    for (int item = tid; item < TT * 15; item += 256) {
        const int t = item / 15, hf = item % 15;
        float a = 0.f;
        #pragma unroll
        for (int i = 0; i < 8; ++i) a = fmaf(s_state[t][i], s_A[i][hf], a);
        s_qk[t][hf] = a;
    }
    __syncthreads();

    const float INV_SQRT5 = 0.44721359549995793f;

    #pragma unroll 1
    for (int pass = 0; pass < 8; ++pass) {
        const int t = pass * 8 + warp;

        float f0[5], f1[5];
        float sc[2][3];
        #pragma unroll
        for (int p = 0; p < 2; ++p) {
            const int n = lane + 32 * p;
            const bool valid = (n < 63);
            const int nn = valid ? n : 0;
            const int j  = (nn < t) ? nn : nn + 1;

            const float c_ = s_cs[j][0];
            const float s_ = s_cs[j][1];
            const float dx0 = s_state[j][0] - s_state[t][0];
            const float dy0 = s_state[j][1] - s_state[t][1];
            const float dx1 = s_state[j][2] - s_state[t][2];
            const float dy1 = s_state[j][3] - s_state[t][3];
            const float xn0 = dx0 * c_ - dy0 * s_;
            const float yn0 = dx0 * s_ + dy0 * c_;
            const float xn1 = dx1 * c_ - dy1 * s_;
            const float yn1 = dx1 * s_ + dy1 * c_;
            const float r    = sqrtf(xn0 * xn0 + yn0 * yn0);
            const float rinv = 1.f / r;
            const float rt   = 1.f / (1.f + __expf(-(1.f - 5.f * (r - 0.2f))));
            float f[5];
            f[0] = valid ? xn0 * rinv : 0.f;
            f[1] = valid ? yn0 * rinv : 0.f;
            f[2] = valid ? xn1 : 0.f;
            f[3] = valid ? yn1 : 0.f;
            f[4] = valid ? rt  : 0.f;
            #pragma unroll
            for (int ff = 0; ff < 5; ++ff) { if (p == 0) f0[ff] = f[ff]; else f1[ff] = f[ff]; }

            #pragma unroll
            for (int h = 0; h < 3; ++h) {
                float d = 0.f;
                #pragma unroll
                for (int ff = 0; ff < 5; ++ff) d = fmaf(f[ff], s_qk[t][h * 5 + ff], d);
                sc[p][h] = valid ? d * INV_SQRT5 : -1e30f;
            }
        }

        float w01[2][3];
        #pragma unroll
        for (int h = 0; h < 3; ++h) {
            float m = fmaxf(sc[0][h], sc[1][h]);
            #pragma unroll
            for (int off = 16; off > 0; off >>= 1)
                m = fmaxf(m, __shfl_xor_sync(0xffffffffu, m, off));
            float e0 = __expf(sc[0][h] - m);
            float e1 = __expf(sc[1][h] - m);
            float s  = e0 + e1;
            #pragma unroll
            for (int off = 16; off > 0; off >>= 1)
                s += __shfl_xor_sync(0xffffffffu, s, off);
            const float si = 1.f / s;
            w01[0][h] = e0 * si;
            w01[1][h] = e1 * si;
        }

        float wf[15];
        #pragma unroll
        for (int h = 0; h < 3; ++h)
            #pragma unroll
            for (int ff = 0; ff < 5; ++ff)
                wf[h * 5 + ff] = fmaf(w01[0][h], f0[ff], w01[1][h] * f1[ff]);
        #pragma unroll
        for (int i = 0; i < 15; ++i)
            #pragma unroll
            for (int off = 16; off > 0; off >>= 1)
                wf[i] += __shfl_xor_sync(0xffffffffu, wf[i], off);

        if (lane == 0) {
            #pragma unroll
            for (int i = 0; i < 15; ++i) s_wf[warp][i] = wf[i];
        }
        __syncwarp();

        const size_t g = (size_t)b * TT + t;
        if (lane < 15) {
            const int h = lane / 5;
            float a = 0.f;
            #pragma unroll
            for (int ff = 0; ff < 5; ++ff)
                a = fmaf(s_wf[warp][h * 5 + ff], s_wv[ff * 15 + lane], a);
            g_xbuf[g * 24 + lane] = a;
        } else if (lane < 23) {
            g_xbuf[g * 24 + lane] = s_state[t][lane - 15];
        }
    }
}

// =====================================================================
// Kernel B: HMMA MLP + heads. 128 tokens/block, 256 threads (8 warps).
// =====================================================================
#define OFF_B1   0
#define OFF_B2   1024
#define OFF_WMU  2048
#define OFF_WLS  4096
#define OFF_WBUF 6144
#define W2LO_OFF 36864          // within WBUF
#define W1LO_OFF 20480          // within WBUF
#define A1HI_OFF 40960          // within WBUF
#define A1LO_OFF 51200          // within WBUF
#define OFF_A2H  79872
#define A2LO_OFF 67584          // A2_lo = OFF_A2H + this
#define SMEM_TOT 215040

__global__ __launch_bounds__(256) void mlp_kernel(
    const float* __restrict__ noise,
    const float* __restrict__ b1g, const float* __restrict__ b2g,
    const float* __restrict__ Wmu, const float* __restrict__ bmu,
    const float* __restrict__ Wls, const float* __restrict__ bls,
    float* __restrict__ out)
{
    extern __shared__ __align__(16) unsigned char smem[];
    const u32 sb  = smem_u32(smem);
    const int tid = threadIdx.x;
    const int wid = tid >> 5;
    const int lane = tid & 31;
    const int tg  = lane & 3;
    const int gid = lane >> 2;

    float* s_b1  = (float*)(smem + OFF_B1);
    float* s_b2  = (float*)(smem + OFF_B2);
    float* s_wmu = (float*)(smem + OFF_WMU);
    float* s_wls = (float*)(smem + OFF_WLS);

    s_b1[tid] = b1g[tid];
    s_b2[tid] = b2g[tid];
    s_wmu[tid] = Wmu[tid]; s_wmu[tid + 256] = Wmu[tid + 256];
    s_wls[tid] = Wls[tid]; s_wls[tid + 256] = Wls[tid + 256];

    // ---- stage x -> A1 bf16 hi/lo ([128][40] stride 80B) ----
    if (tid < 128) {
        const size_t tok = (size_t)blockIdx.x * 128 + tid;
        float x[24];
        const float4* xp = (const float4*)(g_xbuf + tok * 24);
        #pragma unroll
        for (int i = 0; i < 6; ++i) ((float4*)x)[i] = xp[i];
        x[23] = 0.f;
        u32* dh = (u32*)(smem + OFF_WBUF + A1HI_OFF + tid * 80);
        u32* dl = (u32*)(smem + OFF_WBUF + A1LO_OFF + tid * 80);
        #pragma unroll
        for (int i = 0; i < 16; ++i) {
            if (i < 12) {
                float ra, rb;
                dh[i] = pack_hi(x[2 * i], x[2 * i + 1], ra, rb);
                dl[i] = pack_bf(ra, rb);
            } else { dh[i] = 0u; dl[i] = 0u; }
        }
    }
    // ---- copy W1 hi/lo ----
    {
        const uint4* s1 = (const uint4*)g_w1_hi;
        const uint4* s2 = (const uint4*)g_w1_lo;
        uint4* d1 = (uint4*)(smem + OFF_WBUF);
        uint4* d2 = (uint4*)(smem + OFF_WBUF + W1LO_OFF);
        #pragma unroll
        for (int i = 0; i < 5; ++i) { d1[tid + 256 * i] = s1[tid + 256 * i]; d2[tid + 256 * i] = s2[tid + 256 * i]; }
    }
    __syncthreads();

    float acc[32][4];
    #pragma unroll
    for (int j = 0; j < 32; ++j)
        #pragma unroll
        for (int c = 0; c < 4; ++c) acc[j][c] = 0.f;

    // per-thread ldmatrix address components
    const u32 aRowB = (u32)(wid * 16 + (lane & 15));
    const u32 aColB = (u32)(lane & 16);           // byte offset of k-halfword block
    const u32 bRow  = (u32)((lane & 7) + ((lane >> 4) << 3));
    const u32 bKB   = (u32)((lane & 8) << 1);     // byte offset 0/16

    // ---- layer 1: K=32 (2 ksteps) ----
    {
        const u32 aH = sb + OFF_WBUF + A1HI_OFF + aRowB * 80 + aColB;
        const u32 aL = sb + OFF_WBUF + A1LO_OFF + aRowB * 80 + aColB;
        const u32 bH = sb + OFF_WBUF + bRow * 80 + bKB;
        const u32 bL = bH + W1LO_OFF;
        #pragma unroll
        for (int ks = 0; ks < 2; ++ks) {
            u32 ah[4], al[4];
            ldsm_x4(ah, aH + ks * 32);
            ldsm_x4(al, aL + ks * 32);
            #pragma unroll
            for (int jp = 0; jp < 16; ++jp) {
                u32 bh[4], bl[4];
                ldsm_x4(bh, bH + jp * 1280 + ks * 32);
                ldsm_x4(bl, bL + jp * 1280 + ks * 32);
                mma16816(acc[2 * jp], ah, bh[0], bh[1]);
                mma16816(acc[2 * jp], al, bh[0], bh[1]);
                mma16816(acc[2 * jp], ah, bl[0], bl[1]);
                mma16816(acc[2 * jp + 1], ah, bh[2], bh[3]);
                mma16816(acc[2 * jp + 1], al, bh[2], bh[3]);
                mma16816(acc[2 * jp + 1], ah, bl[2], bl[3]);
            }
        }
    }

    // ---- h1 = relu(acc+b1) -> A2 bf16 hi/lo ([128][264] stride 528B) ----
    {
        const int r0 = wid * 16 + gid, r1 = r0 + 8;
        #pragma unroll
        for (int j = 0; j < 32; ++j) {
            const int n0 = j * 8 + tg * 2;
            const float ba = s_b1[n0], bb = s_b1[n0 + 1];
            const float h00 = fmaxf(acc[j][0] + ba, 0.f);
            const float h01 = fmaxf(acc[j][1] + bb, 0.f);
            const float h10 = fmaxf(acc[j][2] + ba, 0.f);
            const float h11 = fmaxf(acc[j][3] + bb, 0.f);
            float ra, rb;
            u32 v = pack_hi(h00, h01, ra, rb);
            *(u32*)(smem + OFF_A2H + r0 * 528 + n0 * 2) = v;
            *(u32*)(smem + OFF_A2H + A2LO_OFF + r0 * 528 + n0 * 2) = pack_bf(ra, rb);
            v = pack_hi(h10, h11, ra, rb);
            *(u32*)(smem + OFF_A2H + r1 * 528 + n0 * 2) = v;
            *(u32*)(smem + OFF_A2H + A2LO_OFF + r1 * 528 + n0 * 2) = pack_bf(ra, rb);
            acc[j][0] = 0.f; acc[j][1] = 0.f; acc[j][2] = 0.f; acc[j][3] = 0.f;
        }
    }

    // ---- layer 2: K=256 in 4 chunks of 64 ----
    const u32 a2H = sb + OFF_A2H + aRowB * 528 + aColB;
    const u32 a2L = a2H + A2LO_OFF;
    const u32 b2H = sb + OFF_WBUF + bRow * 144 + bKB;
    const u32 b2L = b2H + W2LO_OFF;

    #pragma unroll 1
    for (int kc = 0; kc < 4; ++kc) {
        __syncthreads();   // prior users of WBUF done
        {
            const uint4* s1 = (const uint4*)(g_w2_hi + kc * 18432);
            const uint4* s2 = (const uint4*)(g_w2_lo + kc * 18432);
            uint4* d1 = (uint4*)(smem + OFF_WBUF);
            uint4* d2 = (uint4*)(smem + OFF_WBUF + W2LO_OFF);
            #pragma unroll
            for (int i = 0; i < 9; ++i) { d1[tid + 256 * i] = s1[tid + 256 * i]; d2[tid + 256 * i] = s2[tid + 256 * i]; }
        }
        __syncthreads();

        #pragma unroll
        for (int ks = 0; ks < 4; ++ks) {
            u32 ah[4], al[4];
            ldsm_x4(ah, a2H + kc * 128 + ks * 32);
            ldsm_x4(al, a2L + kc * 128 + ks * 32);
            #pragma unroll
            for (int jp = 0; jp < 16; ++jp) {
                u32 bh[4], bl[4];
                ldsm_x4(bh, b2H + jp * 2304 + ks * 32);
                ldsm_x4(bl, b2L + jp * 2304 + ks * 32);
                mma16816(acc[2 * jp], ah, bh[0], bh[1]);
                mma16816(acc[2 * jp], al, bh[0], bh[1]);
                mma16816(acc[2 * jp], ah, bl[0], bl[1]);
                mma16816(acc[2 * jp + 1], ah, bh[2], bh[3]);
                mma16816(acc[2 * jp + 1], al, bh[2], bh[3]);
                mma16816(acc[2 * jp + 1], ah, bl[2], bl[3]);
            }
        }
    }

    // ---- epilogue: heads ----
    float p00 = 0.f, p01 = 0.f, p02 = 0.f, p03 = 0.f;
    float p10 = 0.f, p11 = 0.f, p12 = 0.f, p13 = 0.f;
    #pragma unroll
    for (int j = 0; j < 32; ++j) {
        const int n0 = j * 8 + tg * 2;
        const float ba = s_b2[n0], bb = s_b2[n0 + 1];
        const float h00 = fmaxf(acc[j][0] + ba, 0.f);
        const float h01 = fmaxf(acc[j][1] + bb, 0.f);
        const float h10 = fmaxf(acc[j][2] + ba, 0.f);
        const float h11 = fmaxf(acc[j][3] + bb, 0.f);
        const float m0a = s_wmu[n0 * 2 + 0], m1a = s_wmu[n0 * 2 + 1];
        const float m0b = s_wmu[n0 * 2 + 2], m1b = s_wmu[n0 * 2 + 3];
        const float l0a = s_wls[n0 * 2 + 0], l1a = s_wls[n0 * 2 + 1];
        const float l0b = s_wls[n0 * 2 + 2], l1b = s_wls[n0 * 2 + 3];
        p00 = fmaf(h00, m0a, fmaf(h01, m0b, p00));
        p01 = fmaf(h00, m1a, fmaf(h01, m1b, p01));
        p02 = fmaf(h00, l0a, fmaf(h01, l0b, p02));
        p03 = fmaf(h00, l1a, fmaf(h01, l1b, p03));
        p10 = fmaf(h10, m0a, fmaf(h11, m0b, p10));
        p11 = fmaf(h10, m1a, fmaf(h11, m1b, p11));
        p12 = fmaf(h10, l0a, fmaf(h11, l0b, p12));
        p13 = fmaf(h10, l1a, fmaf(h11, l1b, p13));
    }
    #pragma unroll
    for (int off = 1; off <= 2; off <<= 1) {
        p00 += __shfl_xor_sync(0xffffffffu, p00, off);
        p01 += __shfl_xor_sync(0xffffffffu, p01, off);
        p02 += __shfl_xor_sync(0xffffffffu, p02, off);
        p03 += __shfl_xor_sync(0xffffffffu, p03, off);
        p10 += __shfl_xor_sync(0xffffffffu, p10, off);
        p11 += __shfl_xor_sync(0xffffffffu, p11, off);
        p12 += __shfl_xor_sync(0xffffffffu, p12, off);
        p13 += __shfl_xor_sync(0xffffffffu, p13, off);
    }

    if (tg == 0) {
        const float bm0 = bmu[0], bm1 = bmu[1];
        const float bl0 = bls[0], bl1 = bls[1];
        const float HL2PI = 0.9189385332046727f;
        #pragma unroll
        for (int rr = 0; rr < 2; ++rr) {
            const size_t g = (size_t)blockIdx.x * 128 + wid * 16 + gid + rr * 8;
            const float q0 = rr ? p10 : p00;
            const float q1 = rr ? p11 : p01;
            const float q2 = rr ? p12 : p02;
            const float q3 = rr ? p13 : p03;
            const float mu0 = tanhf(q0 + bm0);
            const float mu1 = tanhf(q1 + bm1);
            const float t0  = tanhf(q2 + bl0);
            const float t1  = tanhf(q3 + bl1);
            const float ls0 = -20.f + 11.f * (t0 + 1.f);
            const float ls1 = -20.f + 11.f * (t1 + 1.f);
            const float sd0 = expf(ls0), sd1 = expf(ls1);
            const float n0 = noise[g * 2 + 0], n1 = noise[g * 2 + 1];
            const float z0 = mu0 + sd0 * n0, z1 = mu1 + sd1 * n1;
            const float a0 = tanhf(z0), a1 = tanhf(z1);
            const float lp0 = -0.5f * n0 * n0 - ls0 - HL2PI - logf(1.f - a0 * a0 + 1e-7f);
            const float lp1 = -0.5f * n1 * n1 - ls1 - HL2PI - logf(1.f - a1 * a1 + 1e-7f);
            out[g * 2 + 0] = a0;
            out[g * 2 + 1] = a1;
            out[(size_t)NTOK * 2 + g] = lp0 + lp1;
        }
    }
}

extern "C" void kernel_launch(void* const* d_in, const int* in_sizes, int n_in,
                              void* d_out, int out_size) {
    const float* state = (const float*)d_in[0];
    const float* noise = (const float*)d_in[1];
    const float* Wq    = (const float*)d_in[2];
    const float* Wk    = (const float*)d_in[3];
    const float* Wv    = (const float*)d_in[4];
    const float* W1    = (const float*)d_in[5];
    const float* b1    = (const float*)d_in[6];
    const float* W2    = (const float*)d_in[7];
    const float* b2    = (const float*)d_in[8];
    const float* Wmu   = (const float*)d_in[9];
    const float* bmu   = (const float*)d_in[10];
    const float* Wls   = (const float*)d_in[11];
    const float* bls   = (const float*)d_in[12];

    cudaFuncSetAttribute(mlp_kernel, cudaFuncAttributeMaxDynamicSharedMemorySize, SMEM_TOT);

    pack_kernel<<<288, 256>>>(W1, W2);
    attn_kernel<<<BB, 256>>>(state, Wq, Wk, Wv);
    mlp_kernel<<<NTOK / 128, 256, SMEM_TOT>>>(noise, b1, b2, Wmu, bmu, Wls, bls,
                                              (float*)d_out);
}